// round 3
// baseline (speedup 1.0000x reference)
#include <cuda_runtime.h>
#include <cuda_bf16.h>

// Problem: B=2, L=256, D=256.
// out = Re(h), h from reverse complex linear recurrence (see analysis).
// Scratch for the complex decay coefficients a[b][d][l]:
__device__ float2 g_A[2 * 256 * 256];

__device__ __forceinline__ float2 cmul(float2 a, float2 b) {
    return make_float2(a.x * b.x - a.y * b.y, a.x * b.y + a.y * b.x);
}
__device__ __forceinline__ float2 cadd(float2 a, float2 b) {
    return make_float2(a.x + b.x, a.y + b.y);
}

// ---------------------------------------------------------------------------
// Kernel 1: GEMM  raw[m,n] = sum_k X[m,k] * W[n,k],  M=N=512, K=256,
// fused epilogue: (re,im) = raw[m,2d],raw[m,2d+1];
//   s = rsqrt(re^2+im^2) * exp(-(re^2+im^2));  a = (re*s, im*s)
// stored as g_A[((b*256+d)*256)+l], m = b*256+l.
// 64x64 block tile, 256 threads, 4x4 per thread, BK=16.
// ---------------------------------------------------------------------------
__global__ __launch_bounds__(256)
void gemm_a_kernel(const float* __restrict__ X, const float* __restrict__ W) {
    __shared__ float As[16][65];
    __shared__ float Bs[16][65];

    const int tid = threadIdx.x;
    const int tx = tid & 15;        // 16 cols of 4 -> n
    const int ty = tid >> 4;        // 16 rows of 4 -> m
    const int m0 = blockIdx.y * 64;
    const int n0 = blockIdx.x * 64;

    float acc[4][4];
#pragma unroll
    for (int i = 0; i < 4; i++)
#pragma unroll
        for (int j = 0; j < 4; j++) acc[i][j] = 0.f;

    for (int k0 = 0; k0 < 256; k0 += 16) {
#pragma unroll
        for (int i = 0; i < 4; i++) {
            int idx = tid + 256 * i;     // 0..1023
            int mm = idx >> 4;           // 0..63
            int kk = idx & 15;           // 0..15
            As[kk][mm] = X[(m0 + mm) * 256 + k0 + kk];
            Bs[kk][mm] = W[(n0 + mm) * 256 + k0 + kk];
        }
        __syncthreads();
#pragma unroll
        for (int kk = 0; kk < 16; kk++) {
            float ar[4], br[4];
#pragma unroll
            for (int i = 0; i < 4; i++) ar[i] = As[kk][ty * 4 + i];
#pragma unroll
            for (int j = 0; j < 4; j++) br[j] = Bs[kk][tx * 4 + j];
#pragma unroll
            for (int i = 0; i < 4; i++)
#pragma unroll
                for (int j = 0; j < 4; j++) acc[i][j] += ar[i] * br[j];
        }
        __syncthreads();
    }

    // Epilogue: n pairs (2d, 2d+1). tx*4 is even, so each thread owns 2 complex
    // outputs per row.
#pragma unroll
    for (int i = 0; i < 4; i++) {
        int m = m0 + ty * 4 + i;
        int bb = m >> 8;
        int l = m & 255;
#pragma unroll
        for (int p = 0; p < 2; p++) {
            int n = n0 + tx * 4 + 2 * p;
            int d = n >> 1;
            float re = acc[i][2 * p];
            float im = acc[i][2 * p + 1];
            float mag2 = re * re + im * im;
            float s = rsqrtf(mag2) * expf(-mag2);
            g_A[((bb * 256 + d) * 256) + l] = make_float2(re * s, im * s);
        }
    }
}

// ---------------------------------------------------------------------------
// Kernel 2: per-(b,d) reverse scan, block-parallel (Hillis-Steele).
// Thread t handles reversed position r=t, i.e. l = 255 - t.
// Element: (A, Y) = (a_l, a_l * xhat_l).
// Combine(cur, prev) [prev = smaller r = larger l = inner segment]:
//   Y' = Y_cur + A_cur * Y_prev ;  A' = A_cur * A_prev.
// g_l = Y at t. Output h_l = g_l + xhat_{l-1} (l>=1), h_255 += x[b,255,d].
// ---------------------------------------------------------------------------
__global__ __launch_bounds__(256)
void scan_kernel(const float* __restrict__ x,
                 const float* __restrict__ h0r,
                 const float* __restrict__ h0i,
                 float* __restrict__ out) {
    const int b = blockIdx.x >> 8;
    const int d = blockIdx.x & 255;
    const int t = threadIdx.x;     // reversed index r
    const int l = 255 - t;
    const int lane = t & 31;
    const int w = t >> 5;

    const float2 a = g_A[((b * 256 + d) * 256) + l];

    float2 xh;
    if (l == 0) xh = make_float2(h0r[d], h0i[d]);
    else        xh = make_float2(x[((b * 256) + (l - 1)) * 256 + d], 0.f);

    float2 A = a;
    float2 Y = cmul(a, xh);

    // Warp-level inclusive scan over r.
    const unsigned mask = 0xffffffffu;
#pragma unroll
    for (int o = 1; o < 32; o <<= 1) {
        float2 pA, pY;
        pA.x = __shfl_up_sync(mask, A.x, o);
        pA.y = __shfl_up_sync(mask, A.y, o);
        pY.x = __shfl_up_sync(mask, Y.x, o);
        pY.y = __shfl_up_sync(mask, Y.y, o);
        if (lane >= o) {
            float2 nY = cadd(Y, cmul(A, pY));
            float2 nA = cmul(A, pA);
            Y = nY;
            A = nA;
        }
    }

    __shared__ float2 aggA[8], aggY[8];
    __shared__ float2 preA[8], preY[8];
    if (lane == 31) { aggA[w] = A; aggY[w] = Y; }
    __syncthreads();
    if (t == 0) {
        float2 pA = make_float2(1.f, 0.f);
        float2 pY = make_float2(0.f, 0.f);
#pragma unroll
        for (int w2 = 0; w2 < 8; w2++) {
            preA[w2] = pA;
            preY[w2] = pY;
            float2 nY = cadd(aggY[w2], cmul(aggA[w2], pY));
            float2 nA = cmul(aggA[w2], pA);
            pA = nA;
            pY = nY;
        }
    }
    __syncthreads();
    if (w > 0) {
        float2 pY = preY[w];
        Y = cadd(Y, cmul(A, pY));
    }

    // h_l real part
    float res = Y.x;
    if (l >= 2)      res += x[((b * 256) + (l - 2)) * 256 + d];
    else if (l == 1) res += h0r[d];
    if (l == 255)    res += x[((b * 256) + 255) * 256 + d];

    out[((b * 256) + l) * 256 + d] = res;
}

extern "C" void kernel_launch(void* const* d_in, const int* in_sizes, int n_in,
                              void* d_out, int out_size) {
    const float* x   = (const float*)d_in[0];
    const float* W   = (const float*)d_in[1];
    const float* h0r = (const float*)d_in[2];
    const float* h0i = (const float*)d_in[3];
    float* out = (float*)d_out;

    dim3 ggrid(8, 8);   // N tiles x M tiles (512/64 each)
    gemm_a_kernel<<<ggrid, 256>>>(x, W);
    scan_kernel<<<512, 256>>>(x, h0r, h0i, out);
}

// round 8
// speedup vs baseline: 1.4942x; 1.4942x over previous
#include <cuda_runtime.h>
#include <cuda_bf16.h>

// B=2, L=256, D=256. Single fused kernel:
//   phase 1: GEMM raw[l, n] for this block's 8 n-columns (n = 8*dg .. 8*dg+7)
//            via packed f32x2 FMA, X staged transposed in smem, W broadcast.
//   phase 2: epilogue a = (re,im) * rsqrt(|.|^2) * exp(-|.|^2) -> smem
//   phase 3: 4 vectorized reverse complex scans (Hillis-Steele) + output.

__device__ __forceinline__ float2 cmul(float2 a, float2 b) {
    return make_float2(a.x * b.x - a.y * b.y, a.x * b.y + a.y * b.x);
}
__device__ __forceinline__ float2 cadd(float2 a, float2 b) {
    return make_float2(a.x + b.x, a.y + b.y);
}

// Shared layout (byte offsets), phase-aliased:
//  phase 1: [0, 32896)  Xs[32][257] floats (transposed tile, pad 257)
//           [32896, 41088) shW[256][8] floats (8 W rows, pair-interleaved)
//  phase 2/3: [0, 8192)   sA[4][256] float2
//             [8192,12288) xsr[4][256] float (real part of xhat)
//             [12288,12544) wagA[4][8] float2
//             [12544,12800) wagY[4][8] float2
//             [12800,13056) preY[4][8] float2
#define SMEM_BYTES 41088

__global__ __launch_bounds__(256)
void sioconv_fused(const float* __restrict__ X, const float* __restrict__ W,
                   const float* __restrict__ h0r, const float* __restrict__ h0i,
                   float* __restrict__ out) {
    __shared__ __align__(16) char smem[SMEM_BYTES];

    const int b  = blockIdx.x >> 6;   // 0..1
    const int dg = blockIdx.x & 63;   // 0..63, d = 4*dg + j
    const int n0 = dg * 8;
    const int t  = threadIdx.x;

    float* Xs  = (float*)smem;            // [32][257]
    float* shW = (float*)(smem + 32896);  // [256][8]: shW[k][n] = W[n0+n][k]

    const float* Xb = X + b * 256 * 256;

    // Load the 8 W rows (pair-contiguous per k so LDS.128 gives 2 f32x2 pairs).
#pragma unroll
    for (int i = 0; i < 8; i++) {
        int e = t + 256 * i;         // 0..2047
        int n = e >> 8;              // 0..7
        int k = e & 255;
        shW[k * 8 + n] = W[(n0 + n) * 256 + k];
    }

    // acc[j] packs (raw[l, 2j], raw[l, 2j+1]) as f32x2; 0ull == (+0,+0).
    unsigned long long acc[4] = {0ull, 0ull, 0ull, 0ull};

    for (int k0 = 0; k0 < 256; k0 += 32) {
        __syncthreads();   // previous tile's Xs reads done (also covers shW load)
        // Stage X tile transposed: Xs[kk][l], conflict-free (pad 257).
#pragma unroll
        for (int i = 0; i < 8; i++) {
            int e = t + 256 * i;     // float4 index, 0..2047
            int l = e >> 3;          // 0..255
            int c = (e & 7) * 4;     // kk base 0..28
            float4 v = *(const float4*)(Xb + l * 256 + k0 + c);
            Xs[(c + 0) * 257 + l] = v.x;
            Xs[(c + 1) * 257 + l] = v.y;
            Xs[(c + 2) * 257 + l] = v.z;
            Xs[(c + 3) * 257 + l] = v.w;
        }
        __syncthreads();

#pragma unroll
        for (int kk = 0; kk < 32; kk++) {
            float xv = Xs[kk * 257 + t];              // l = t, broadcast-free
            unsigned long long x2;
            asm("mov.b64 %0, {%1, %1};" : "=l"(x2) : "f"(xv));
            const ulonglong2* wrow =
                (const ulonglong2*)(shW + (k0 + kk) * 8);
            ulonglong2 wA = wrow[0];   // pairs (n0,n1) (n2,n3) — broadcast
            ulonglong2 wB = wrow[1];   // pairs (n4,n5) (n6,n7)
            asm("fma.rn.f32x2 %0, %1, %2, %0;" : "+l"(acc[0]) : "l"(x2), "l"(wA.x));
            asm("fma.rn.f32x2 %0, %1, %2, %0;" : "+l"(acc[1]) : "l"(x2), "l"(wA.y));
            asm("fma.rn.f32x2 %0, %1, %2, %0;" : "+l"(acc[2]) : "l"(x2), "l"(wB.x));
            asm("fma.rn.f32x2 %0, %1, %2, %0;" : "+l"(acc[3]) : "l"(x2), "l"(wB.y));
        }
    }

    __syncthreads();   // all Xs/shW reads done; safe to alias

    float2* sA  = (float2*)smem;            // [4][256]
    float*  xsr = (float*)(smem + 8192);    // [4][256]
    float2* wagA = (float2*)(smem + 12288); // [4][8]
    float2* wagY = (float2*)(smem + 12544); // [4][8]
    float2* preY = (float2*)(smem + 12800); // [4][8]

    // Epilogue: thread t holds l = t for 4 d's.
#pragma unroll
    for (int j = 0; j < 4; j++) {
        float re, im;
        asm("mov.b64 {%0, %1}, %2;" : "=f"(re), "=f"(im) : "l"(acc[j]));
        float mag2 = re * re + im * im;
        float s = rsqrtf(mag2) * expf(-mag2);
        sA[j * 256 + t] = make_float2(re * s, im * s);
    }

    // Stage xhat real parts: xsr[j][l] = (l==0) ? h0r[d] : x[b, l-1, d].
#pragma unroll
    for (int i = 0; i < 4; i++) {
        int e = t + 256 * i;
        int l = e >> 2;
        int j = e & 3;
        int d = dg * 4 + j;
        xsr[j * 256 + l] = (l == 0) ? h0r[d] : Xb[(l - 1) * 256 + d];
    }
    __syncthreads();

    // Scan: thread t handles reversed index r = t, i.e. l = 255 - t.
    const int l = 255 - t;
    const int lane = t & 31;
    const int w = t >> 5;

    float2 A[4], Y[4];
#pragma unroll
    for (int j = 0; j < 4; j++) {
        float2 a = sA[j * 256 + l];
        float2 xh;
        xh.x = xsr[j * 256 + l];
        xh.y = (l == 0) ? h0i[dg * 4 + j] : 0.f;
        A[j] = a;
        Y[j] = cmul(a, xh);
    }

    const unsigned mask = 0xffffffffu;
#pragma unroll
    for (int o = 1; o < 32; o <<= 1) {
#pragma unroll
        for (int j = 0; j < 4; j++) {
            float2 pA, pY;
            pA.x = __shfl_up_sync(mask, A[j].x, o);
            pA.y = __shfl_up_sync(mask, A[j].y, o);
            pY.x = __shfl_up_sync(mask, Y[j].x, o);
            pY.y = __shfl_up_sync(mask, Y[j].y, o);
            if (lane >= o) {
                float2 nY = cadd(Y[j], cmul(A[j], pY));
                float2 nA = cmul(A[j], pA);
                Y[j] = nY;
                A[j] = nA;
            }
        }
    }

    if (lane == 31) {
#pragma unroll
        for (int j = 0; j < 4; j++) {
            wagA[j * 8 + w] = A[j];
            wagY[j * 8 + w] = Y[j];
        }
    }
    __syncthreads();
    if (t < 4) {
        int j = t;
        float2 pY = make_float2(0.f, 0.f);
#pragma unroll
        for (int w2 = 0; w2 < 8; w2++) {
            preY[j * 8 + w2] = pY;
            pY = cadd(wagY[j * 8 + w2], cmul(wagA[j * 8 + w2], pY));
        }
    }
    __syncthreads();

    float res[4];
#pragma unroll
    for (int j = 0; j < 4; j++) {
        float2 Yf = Y[j];
        if (w > 0) Yf = cadd(Yf, cmul(A[j], preY[j * 8 + w]));
        float r = Yf.x;
        if (l >= 1)   r += xsr[j * 256 + (l - 1)];  // Re(xhat[l-1]); xsr[0]=h0r
        if (l == 255) r += Xb[255 * 256 + dg * 4 + j];
        res[j] = r;
    }
    *(float4*)(out + (b * 256 + l) * 256 + dg * 4) =
        make_float4(res[0], res[1], res[2], res[3]);
}

extern "C" void kernel_launch(void* const* d_in, const int* in_sizes, int n_in,
                              void* d_out, int out_size) {
    const float* x   = (const float*)d_in[0];
    const float* W   = (const float*)d_in[1];
    const float* h0r = (const float*)d_in[2];
    const float* h0i = (const float*)d_in[3];
    float* out = (float*)d_out;

    sioconv_fused<<<128, 256>>>(x, W, h0r, h0i, out);
}